// round 8
// baseline (speedup 1.0000x reference)
#include <cuda_runtime.h>
#include <cuda_bf16.h>
#include <cstdint>

// Problem shape: A [64, 2048, 64], B [64, 64, 2048], out [64, 2048, 2048] (batch=4*16 flattened)
#define NBATCH 64
#define SDIM   2048
#define TDIM   2048
#define DDIM   64
#define NA_EL  (NBATCH * SDIM * DDIM)   // 8388608
#define NB_EL  (NBATCH * DDIM * TDIM)   // 8388608
#define MM_BLOCKS 1024                  // minmax blocks per tensor
#define NTILES  (NBATCH * 16 * 16)      // 16384 output tiles of 128x128
#define GEMM_GRID 296                   // 2 CTAs per SM (148 SMs)

// ---- device-global state (scratch; no allocations allowed) ----
__device__ float g_pmin[2][MM_BLOCKS], g_pmax[2][MM_BLOCKS];
__device__ float g_scale;
__device__ __nv_bfloat16 g_Aq[NA_EL];
__device__ __nv_bfloat16 g_Bq[NB_EL];

// ---- pass 1: per-tensor min/max partials (deterministic, no atomics, no reset) ----
__global__ void __launch_bounds__(256) k_minmax(const float* __restrict__ A,
                                               const float* __restrict__ B) {
    const int sel = blockIdx.z;
    const float4* x4 = (const float4*)(sel ? B : A);
    const int n4 = NA_EL / 4;
    float vmin = 0.0f, vmax = 0.0f;
    for (int i = blockIdx.x * blockDim.x + threadIdx.x; i < n4;
         i += MM_BLOCKS * blockDim.x) {
        float4 v = x4[i];
        vmin = fminf(vmin, fminf(fminf(v.x, v.y), fminf(v.z, v.w)));
        vmax = fmaxf(vmax, fmaxf(fmaxf(v.x, v.y), fmaxf(v.z, v.w)));
    }
    #pragma unroll
    for (int o = 16; o > 0; o >>= 1) {
        vmin = fminf(vmin, __shfl_xor_sync(0xffffffffu, vmin, o));
        vmax = fmaxf(vmax, __shfl_xor_sync(0xffffffffu, vmax, o));
    }
    __shared__ float smin[8], smax[8];
    int wid = threadIdx.x >> 5, lane = threadIdx.x & 31;
    if (lane == 0) { smin[wid] = vmin; smax[wid] = vmax; }
    __syncthreads();
    if (threadIdx.x == 0) {
        float m = smin[0], M = smax[0];
        #pragma unroll
        for (int w = 1; w < 8; w++) { m = fminf(m, smin[w]); M = fmaxf(M, smax[w]); }
        g_pmin[sel][blockIdx.x] = m;
        g_pmax[sel][blockIdx.x] = M;
    }
}

// ---- pass 2: quant params (recomputed per block; deterministic) + fake-quant ----
__global__ void __launch_bounds__(256) k_quant(const float* __restrict__ A,
                                               const float* __restrict__ B) {
    const int t = threadIdx.x;
    // reduce 1024 partials per tensor: thread t covers t, t+256, t+512, t+768
    float mA =  1e30f, MA = -1e30f, mB =  1e30f, MB = -1e30f;
    #pragma unroll
    for (int j = 0; j < MM_BLOCKS / 256; j++) {
        int idx = t + j * 256;
        mA = fminf(mA, g_pmin[0][idx]); MA = fmaxf(MA, g_pmax[0][idx]);
        mB = fminf(mB, g_pmin[1][idx]); MB = fmaxf(MB, g_pmax[1][idx]);
    }
    #pragma unroll
    for (int o = 16; o > 0; o >>= 1) {
        mA = fminf(mA, __shfl_xor_sync(0xffffffffu, mA, o));
        MA = fmaxf(MA, __shfl_xor_sync(0xffffffffu, MA, o));
        mB = fminf(mB, __shfl_xor_sync(0xffffffffu, mB, o));
        MB = fmaxf(MB, __shfl_xor_sync(0xffffffffu, MB, o));
    }
    __shared__ float sred[4][8];
    __shared__ float s_delta, s_zp;
    int wid = t >> 5, lane = t & 31;
    if (lane == 0) { sred[0][wid] = mA; sred[1][wid] = MA; sred[2][wid] = mB; sred[3][wid] = MB; }
    __syncthreads();
    if (t == 0) {
        float minA = sred[0][0], maxA = sred[1][0], minB = sred[2][0], maxB = sred[3][0];
        #pragma unroll
        for (int w = 1; w < 8; w++) {
            minA = fminf(minA, sred[0][w]); maxA = fmaxf(maxA, sred[1][w]);
            minB = fminf(minB, sred[2][w]); maxB = fmaxf(maxB, sred[3][w]);
        }
        float dA = fmaxf(__fdiv_rn(maxA - minA, 255.0f), 1e-8f);
        float dB = fmaxf(__fdiv_rn(maxB - minB, 255.0f), 1e-8f);
        if (blockIdx.z == 0) {
            s_delta = dA;
            s_zp = rintf(__fdiv_rn(-minA, dA));
        } else {
            s_delta = dB;
            s_zp = rintf(__fdiv_rn(-minB, dB));
        }
        if (blockIdx.x == 0 && blockIdx.z == 0) g_scale = dA * dB;
    }
    __syncthreads();
    const float delta = s_delta, zp = s_zp;

    const int sel = blockIdx.z;
    const float4* x4 = (const float4*)(sel ? B : A);
    uint2* o2 = (uint2*)(sel ? g_Bq : g_Aq);
    const int n4 = NA_EL / 4;
    for (int i = blockIdx.x * blockDim.x + t; i < n4; i += 2048 * 256) {
        float4 v = x4[i];
        float q0 = fminf(fmaxf(rintf(__fdiv_rn(v.x, delta)) + zp, 0.0f), 255.0f) - zp;
        float q1 = fminf(fmaxf(rintf(__fdiv_rn(v.y, delta)) + zp, 0.0f), 255.0f) - zp;
        float q2 = fminf(fmaxf(rintf(__fdiv_rn(v.z, delta)) + zp, 0.0f), 255.0f) - zp;
        float q3 = fminf(fmaxf(rintf(__fdiv_rn(v.w, delta)) + zp, 0.0f), 255.0f) - zp;
        __nv_bfloat162 p0 = __floats2bfloat162_rn(q0, q1);
        __nv_bfloat162 p1 = __floats2bfloat162_rn(q2, q3);
        uint2 u;
        u.x = *(uint32_t*)&p0;
        u.y = *(uint32_t*)&p1;
        o2[i] = u;
    }
}

// ---- pass 3: persistent batched GEMM, CTA tile 128x128, 3-stage cp.async ----
// Epilogue is staged through the (now-free) current input stage's smem and
// written back with one full 512B output row per warp-instruction (STG.128,
// 100% line utilization) instead of 8-row-scattered STG.64 (32B/line).
#define SA_ROWS 128
#define SA_COLS 72     // 64 + 8 pad (16B row shift -> no LDSM conflicts)
#define SB_ROWS 64
#define SB_COLS 136    // 128 + 8 pad
#define SA_BYTES (SA_ROWS * SA_COLS * 2)
#define SB_BYTES (SB_ROWS * SB_COLS * 2)
#define STAGE_BYTES (SA_BYTES + SB_BYTES)      // 35840
#define NSTAGE 3
#define SMEM_DYN (NSTAGE * STAGE_BYTES)        // 107520 B (2 CTAs = 215KB <= 228KB)
#define STG_PITCH 136                          // f32 staging pitch: 8-bank shift/row

__device__ __forceinline__ void cpa16(void* dst, const void* src) {
    uint32_t d = (uint32_t)__cvta_generic_to_shared(dst);
    asm volatile("cp.async.cg.shared.global [%0], [%1], 16;" :: "r"(d), "l"(src));
}

__global__ void __launch_bounds__(256, 2) k_gemm(float* __restrict__ out) {
    extern __shared__ char smem_raw[];

    const int tid = threadIdx.x;
    const int warp = tid >> 5, lane = tid & 31;
    const int wm = warp >> 2;      // 0..1 -> 64 rows each
    const int wn = warp & 3;       // 0..3 -> 32 cols each

    const int ar = tid >> 3, ac = (tid & 7) * 8;          // A rows ar+{0,32,64,96}
    const int br = tid >> 4, bc = (tid & 15) * 8;         // B rows br+{0,16,32,48}

    auto stageA = [&](int st) -> __nv_bfloat16 (*)[SA_COLS] {
        return (__nv_bfloat16 (*)[SA_COLS])(smem_raw + st * STAGE_BYTES);
    };
    auto stageB = [&](int st) -> __nv_bfloat16 (*)[SB_COLS] {
        return (__nv_bfloat16 (*)[SB_COLS])(smem_raw + st * STAGE_BYTES + SA_BYTES);
    };

    auto load_tiles = [&](int st, int t) {
        int b  = t >> 8;
        int m0 = ((t >> 4) & 15) * 128;
        int n0 = (t & 15) * 128;
        const __nv_bfloat16* Ab = g_Aq + (size_t)b * SDIM * DDIM + (size_t)m0 * DDIM;
        const __nv_bfloat16* Bb = g_Bq + (size_t)b * DDIM * TDIM + n0;
        __nv_bfloat16 (*sA)[SA_COLS] = stageA(st);
        __nv_bfloat16 (*sB)[SB_COLS] = stageB(st);
        #pragma unroll
        for (int it = 0; it < 4; it++)
            cpa16(&sA[ar + it * 32][ac], Ab + (ar + it * 32) * DDIM + ac);
        #pragma unroll
        for (int it = 0; it < 4; it++)
            cpa16(&sB[br + it * 16][bc], Bb + (size_t)(br + it * 16) * TDIM + bc);
        asm volatile("cp.async.commit_group;");
    };

    const float s = g_scale;

    int t = blockIdx.x;
    int st = 0;
    if (t < NTILES) load_tiles(0, t);
    if (t + GEMM_GRID < NTILES) load_tiles(1, t + GEMM_GRID);

    while (t < NTILES) {
        if (t + GEMM_GRID < NTILES) {
            asm volatile("cp.async.wait_group 1;");   // this tile's group done
        } else {
            asm volatile("cp.async.wait_group 0;");
        }
        __syncthreads();   // also fences iteration i-1's epilogue staging

        __nv_bfloat16 (*sA)[SA_COLS] = stageA(st);
        __nv_bfloat16 (*sB)[SB_COLS] = stageB(st);

        float acc[4][4][4];
        #pragma unroll
        for (int mi = 0; mi < 4; mi++)
            #pragma unroll
            for (int ni = 0; ni < 4; ni++)
                #pragma unroll
                for (int q = 0; q < 4; q++) acc[mi][ni][q] = 0.0f;

        #pragma unroll
        for (int ks = 0; ks < 4; ks++) {
            const int k0 = ks * 16;
            uint32_t af[4][4];
            #pragma unroll
            for (int mi = 0; mi < 4; mi++) {
                int r = wm * 64 + mi * 16 + (lane & 15);
                int c = k0 + (lane >> 4) * 8;
                uint32_t addr = (uint32_t)__cvta_generic_to_shared(&sA[r][c]);
                asm volatile(
                    "ldmatrix.sync.aligned.m8n8.x4.shared.b16 {%0,%1,%2,%3}, [%4];"
                    : "=r"(af[mi][0]), "=r"(af[mi][1]), "=r"(af[mi][2]), "=r"(af[mi][3])
                    : "r"(addr));
            }
            uint32_t bf[4][2];
            #pragma unroll
            for (int nj = 0; nj < 2; nj++) {
                int r = k0 + (lane & 7) + ((lane >> 3) & 1) * 8;
                int c = wn * 32 + nj * 16 + (lane >> 4) * 8;
                uint32_t addr = (uint32_t)__cvta_generic_to_shared(&sB[r][c]);
                uint32_t t0, t1, t2, t3;
                asm volatile(
                    "ldmatrix.sync.aligned.m8n8.x4.trans.shared.b16 {%0,%1,%2,%3}, [%4];"
                    : "=r"(t0), "=r"(t1), "=r"(t2), "=r"(t3)
                    : "r"(addr));
                bf[nj * 2 + 0][0] = t0; bf[nj * 2 + 0][1] = t1;
                bf[nj * 2 + 1][0] = t2; bf[nj * 2 + 1][1] = t3;
            }
            #pragma unroll
            for (int mi = 0; mi < 4; mi++)
                #pragma unroll
                for (int ni = 0; ni < 4; ni++) {
                    asm volatile(
                        "mma.sync.aligned.m16n8k16.row.col.f32.bf16.bf16.f32 "
                        "{%0,%1,%2,%3}, {%4,%5,%6,%7}, {%8,%9}, {%0,%1,%2,%3};"
                        : "+f"(acc[mi][ni][0]), "+f"(acc[mi][ni][1]),
                          "+f"(acc[mi][ni][2]), "+f"(acc[mi][ni][3])
                        : "r"(af[mi][0]), "r"(af[mi][1]), "r"(af[mi][2]), "r"(af[mi][3]),
                          "r"(bf[ni][0]), "r"(bf[ni][1]));
                }
        }

        // prefetch tile i+2 now (safe: top barrier ensured iter i-1 fully done,
        // and stage (st+2)%3 is untouched by iter i). Streams during epilogue.
        if (t + 2 * GEMM_GRID < NTILES)
            load_tiles((st + 2) % NSTAGE, t + 2 * GEMM_GRID);

        // ---- staged epilogue: 2 chunks of 64 rows through stage st's smem ----
        {
            int b  = t >> 8;
            int m0 = ((t >> 4) & 15) * 128;
            int n0 = (t & 15) * 128;
            float* ob = out + (size_t)b * SDIM * TDIM + n0;
            float* stg = (float*)(smem_raw + st * STAGE_BYTES);  // 64*136*4 = 34816B

            #pragma unroll
            for (int c = 0; c < 2; c++) {
                __syncthreads();   // buffer free (compute done / prev chunk drained)
                #pragma unroll
                for (int mm = 0; mm < 2; mm++) {
                    const int mi = 2 * c + mm;
                    const int lr0 = wm * 32 + mm * 16 + (lane >> 2);
                    #pragma unroll
                    for (int ni = 0; ni < 4; ni++) {
                        const int col = wn * 32 + ni * 8 + (lane & 3) * 2;
                        float2 v0 = make_float2(acc[mi][ni][0] * s, acc[mi][ni][1] * s);
                        float2 v1 = make_float2(acc[mi][ni][2] * s, acc[mi][ni][3] * s);
                        *(float2*)&stg[lr0 * STG_PITCH + col]       = v0;
                        *(float2*)&stg[(lr0 + 8) * STG_PITCH + col] = v1;
                    }
                }
                __syncthreads();
                // coalesced drain: warp-instruction = one full 512B output row
                #pragma unroll
                for (int i = 0; i < 8; i++) {
                    int L = i * 256 + tid;
                    int lr = L >> 5;          // 0..63
                    int seg = L & 31;         // 16B segment within row
                    float4 v = *(float4*)&stg[lr * STG_PITCH + seg * 4];
                    int gr = m0 + ((lr & 32) ? 64 : 0) + c * 32 + (lr & 31);
                    *(float4*)&ob[(size_t)gr * TDIM + seg * 4] = v;
                }
            }
        }

        st = (st + 1) % NSTAGE;
        t += GEMM_GRID;
    }
}

extern "C" void kernel_launch(void* const* d_in, const int* in_sizes, int n_in,
                              void* d_out, int out_size) {
    const float* A = (const float*)d_in[0];
    const float* B = (const float*)d_in[1];
    float* out = (float*)d_out;

    cudaFuncSetAttribute(k_gemm, cudaFuncAttributeMaxDynamicSharedMemorySize, SMEM_DYN);

    k_minmax<<<dim3(MM_BLOCKS, 1, 2), 256>>>(A, B);
    k_quant<<<dim3(2048, 1, 2), 256>>>(A, B);
    k_gemm<<<GEMM_GRID, 256, SMEM_DYN>>>(out);
}

// round 9
// speedup vs baseline: 1.0325x; 1.0325x over previous
#include <cuda_runtime.h>
#include <cuda_bf16.h>
#include <cstdint>

// Problem shape: A [64, 2048, 64], B [64, 64, 2048], out [64, 2048, 2048] (batch=4*16 flattened)
#define NBATCH 64
#define SDIM   2048
#define TDIM   2048
#define DDIM   64
#define NA_EL  (NBATCH * SDIM * DDIM)   // 8388608
#define NB_EL  (NBATCH * DDIM * TDIM)   // 8388608
#define MM_BLOCKS 1024                  // minmax blocks per tensor
#define NTILES  (NBATCH * 16 * 16)      // 16384 output tiles of 128x128
#define GEMM_GRID 296                   // 2 CTAs per SM (148 SMs)

// ---- device-global state (scratch; no allocations allowed) ----
__device__ float g_pmin[2][MM_BLOCKS], g_pmax[2][MM_BLOCKS];
__device__ float g_scale;
__device__ __nv_bfloat16 g_Aq[NA_EL];
__device__ __nv_bfloat16 g_Bq[NB_EL];

// ---- pass 1: per-tensor min/max partials (deterministic, no atomics, no reset) ----
__global__ void __launch_bounds__(256) k_minmax(const float* __restrict__ A,
                                               const float* __restrict__ B) {
    const int sel = blockIdx.z;
    const float4* x4 = (const float4*)(sel ? B : A);
    const int n4 = NA_EL / 4;
    float vmin = 0.0f, vmax = 0.0f;
    for (int i = blockIdx.x * blockDim.x + threadIdx.x; i < n4;
         i += MM_BLOCKS * blockDim.x) {
        float4 v = x4[i];
        vmin = fminf(vmin, fminf(fminf(v.x, v.y), fminf(v.z, v.w)));
        vmax = fmaxf(vmax, fmaxf(fmaxf(v.x, v.y), fmaxf(v.z, v.w)));
    }
    #pragma unroll
    for (int o = 16; o > 0; o >>= 1) {
        vmin = fminf(vmin, __shfl_xor_sync(0xffffffffu, vmin, o));
        vmax = fmaxf(vmax, __shfl_xor_sync(0xffffffffu, vmax, o));
    }
    __shared__ float smin[8], smax[8];
    int wid = threadIdx.x >> 5, lane = threadIdx.x & 31;
    if (lane == 0) { smin[wid] = vmin; smax[wid] = vmax; }
    __syncthreads();
    if (threadIdx.x == 0) {
        float m = smin[0], M = smax[0];
        #pragma unroll
        for (int w = 1; w < 8; w++) { m = fminf(m, smin[w]); M = fmaxf(M, smax[w]); }
        g_pmin[sel][blockIdx.x] = m;
        g_pmax[sel][blockIdx.x] = M;
    }
}

// ---- pass 2: quant params (recomputed per block; deterministic) + fake-quant ----
__global__ void __launch_bounds__(256) k_quant(const float* __restrict__ A,
                                               const float* __restrict__ B) {
    const int t = threadIdx.x;
    float mA =  1e30f, MA = -1e30f, mB =  1e30f, MB = -1e30f;
    #pragma unroll
    for (int j = 0; j < MM_BLOCKS / 256; j++) {
        int idx = t + j * 256;
        mA = fminf(mA, g_pmin[0][idx]); MA = fmaxf(MA, g_pmax[0][idx]);
        mB = fminf(mB, g_pmin[1][idx]); MB = fmaxf(MB, g_pmax[1][idx]);
    }
    #pragma unroll
    for (int o = 16; o > 0; o >>= 1) {
        mA = fminf(mA, __shfl_xor_sync(0xffffffffu, mA, o));
        MA = fmaxf(MA, __shfl_xor_sync(0xffffffffu, MA, o));
        mB = fminf(mB, __shfl_xor_sync(0xffffffffu, mB, o));
        MB = fmaxf(MB, __shfl_xor_sync(0xffffffffu, MB, o));
    }
    __shared__ float sred[4][8];
    __shared__ float s_delta, s_zp;
    int wid = t >> 5, lane = t & 31;
    if (lane == 0) { sred[0][wid] = mA; sred[1][wid] = MA; sred[2][wid] = mB; sred[3][wid] = MB; }
    __syncthreads();
    if (t == 0) {
        float minA = sred[0][0], maxA = sred[1][0], minB = sred[2][0], maxB = sred[3][0];
        #pragma unroll
        for (int w = 1; w < 8; w++) {
            minA = fminf(minA, sred[0][w]); maxA = fmaxf(maxA, sred[1][w]);
            minB = fminf(minB, sred[2][w]); maxB = fmaxf(maxB, sred[3][w]);
        }
        float dA = fmaxf(__fdiv_rn(maxA - minA, 255.0f), 1e-8f);
        float dB = fmaxf(__fdiv_rn(maxB - minB, 255.0f), 1e-8f);
        if (blockIdx.z == 0) {
            s_delta = dA;
            s_zp = rintf(__fdiv_rn(-minA, dA));
        } else {
            s_delta = dB;
            s_zp = rintf(__fdiv_rn(-minB, dB));
        }
        if (blockIdx.x == 0 && blockIdx.z == 0) g_scale = dA * dB;
    }
    __syncthreads();
    const float delta = s_delta, zp = s_zp;

    const int sel = blockIdx.z;
    const float4* x4 = (const float4*)(sel ? B : A);
    uint2* o2 = (uint2*)(sel ? g_Bq : g_Aq);
    const int n4 = NA_EL / 4;
    for (int i = blockIdx.x * blockDim.x + t; i < n4; i += 2048 * 256) {
        float4 v = x4[i];
        float q0 = fminf(fmaxf(rintf(__fdiv_rn(v.x, delta)) + zp, 0.0f), 255.0f) - zp;
        float q1 = fminf(fmaxf(rintf(__fdiv_rn(v.y, delta)) + zp, 0.0f), 255.0f) - zp;
        float q2 = fminf(fmaxf(rintf(__fdiv_rn(v.z, delta)) + zp, 0.0f), 255.0f) - zp;
        float q3 = fminf(fmaxf(rintf(__fdiv_rn(v.w, delta)) + zp, 0.0f), 255.0f) - zp;
        __nv_bfloat162 p0 = __floats2bfloat162_rn(q0, q1);
        __nv_bfloat162 p1 = __floats2bfloat162_rn(q2, q3);
        uint2 u;
        u.x = *(uint32_t*)&p0;
        u.y = *(uint32_t*)&p1;
        o2[i] = u;
    }
}

// ---- pass 3: persistent batched GEMM, CTA tile 128x128, 3-stage cp.async ----
// Warp-PRIVATE staged epilogue: each warp transposes its 64x32 fragment region
// through its own smem patch (in the dead current input stage), chunked 16 rows
// at a time, using only __syncwarp. Result: STG.128 at 100% line utilization
// (4 wf / 512B) instead of 8-row-scattered STG.64 (8 wf / 256B). Stores remain
// fire-and-forget; only ONE extra CTA barrier (after compute) per tile.
#define SA_ROWS 128
#define SA_COLS 72     // 64 + 8 pad (16B row shift -> no LDSM conflicts)
#define SB_ROWS 64
#define SB_COLS 136    // 128 + 8 pad
#define SA_BYTES (SA_ROWS * SA_COLS * 2)
#define SB_BYTES (SB_ROWS * SB_COLS * 2)
#define STAGE_BYTES (SA_BYTES + SB_BYTES)      // 35840
#define NSTAGE 3
#define SMEM_DYN (NSTAGE * STAGE_BYTES)        // 107520 B (2 CTAs = 215KB <= 228KB)
#define WST_PITCH 36                           // f32 staging pitch (rows shift 4 banks)
#define WST_FLOATS (16 * WST_PITCH)            // 576 floats = 2304B per warp patch

__device__ __forceinline__ void cpa16(void* dst, const void* src) {
    uint32_t d = (uint32_t)__cvta_generic_to_shared(dst);
    asm volatile("cp.async.cg.shared.global [%0], [%1], 16;" :: "r"(d), "l"(src));
}

__global__ void __launch_bounds__(256, 2) k_gemm(float* __restrict__ out) {
    extern __shared__ char smem_raw[];

    const int tid = threadIdx.x;
    const int warp = tid >> 5, lane = tid & 31;
    const int wm = warp >> 2;      // 0..1 -> 64 rows each
    const int wn = warp & 3;       // 0..3 -> 32 cols each

    const int ar = tid >> 3, ac = (tid & 7) * 8;          // A rows ar+{0,32,64,96}
    const int br = tid >> 4, bc = (tid & 15) * 8;         // B rows br+{0,16,32,48}

    auto stageA = [&](int st) -> __nv_bfloat16 (*)[SA_COLS] {
        return (__nv_bfloat16 (*)[SA_COLS])(smem_raw + st * STAGE_BYTES);
    };
    auto stageB = [&](int st) -> __nv_bfloat16 (*)[SB_COLS] {
        return (__nv_bfloat16 (*)[SB_COLS])(smem_raw + st * STAGE_BYTES + SA_BYTES);
    };

    auto load_tiles = [&](int st, int t) {
        int b  = t >> 8;
        int m0 = ((t >> 4) & 15) * 128;
        int n0 = (t & 15) * 128;
        const __nv_bfloat16* Ab = g_Aq + (size_t)b * SDIM * DDIM + (size_t)m0 * DDIM;
        const __nv_bfloat16* Bb = g_Bq + (size_t)b * DDIM * TDIM + n0;
        __nv_bfloat16 (*sA)[SA_COLS] = stageA(st);
        __nv_bfloat16 (*sB)[SB_COLS] = stageB(st);
        #pragma unroll
        for (int it = 0; it < 4; it++)
            cpa16(&sA[ar + it * 32][ac], Ab + (ar + it * 32) * DDIM + ac);
        #pragma unroll
        for (int it = 0; it < 4; it++)
            cpa16(&sB[br + it * 16][bc], Bb + (size_t)(br + it * 16) * TDIM + bc);
        asm volatile("cp.async.commit_group;");
    };

    const float s = g_scale;

    int t = blockIdx.x;
    int st = 0;
    if (t < NTILES) load_tiles(0, t);
    if (t + GEMM_GRID < NTILES) load_tiles(1, t + GEMM_GRID);

    while (t < NTILES) {
        if (t + GEMM_GRID < NTILES) {
            asm volatile("cp.async.wait_group 1;");   // this tile's group done
        } else {
            asm volatile("cp.async.wait_group 0;");
        }
        __syncthreads();   // stage st ready; prev iter fully complete everywhere

        __nv_bfloat16 (*sA)[SA_COLS] = stageA(st);
        __nv_bfloat16 (*sB)[SB_COLS] = stageB(st);

        float acc[4][4][4];
        #pragma unroll
        for (int mi = 0; mi < 4; mi++)
            #pragma unroll
            for (int ni = 0; ni < 4; ni++)
                #pragma unroll
                for (int q = 0; q < 4; q++) acc[mi][ni][q] = 0.0f;

        #pragma unroll
        for (int ks = 0; ks < 4; ks++) {
            const int k0 = ks * 16;
            uint32_t af[4][4];
            #pragma unroll
            for (int mi = 0; mi < 4; mi++) {
                int r = wm * 64 + mi * 16 + (lane & 15);
                int c = k0 + (lane >> 4) * 8;
                uint32_t addr = (uint32_t)__cvta_generic_to_shared(&sA[r][c]);
                asm volatile(
                    "ldmatrix.sync.aligned.m8n8.x4.shared.b16 {%0,%1,%2,%3}, [%4];"
                    : "=r"(af[mi][0]), "=r"(af[mi][1]), "=r"(af[mi][2]), "=r"(af[mi][3])
                    : "r"(addr));
            }
            uint32_t bf[4][2];
            #pragma unroll
            for (int nj = 0; nj < 2; nj++) {
                int r = k0 + (lane & 7) + ((lane >> 3) & 1) * 8;
                int c = wn * 32 + nj * 16 + (lane >> 4) * 8;
                uint32_t addr = (uint32_t)__cvta_generic_to_shared(&sB[r][c]);
                uint32_t t0, t1, t2, t3;
                asm volatile(
                    "ldmatrix.sync.aligned.m8n8.x4.trans.shared.b16 {%0,%1,%2,%3}, [%4];"
                    : "=r"(t0), "=r"(t1), "=r"(t2), "=r"(t3)
                    : "r"(addr));
                bf[nj * 2 + 0][0] = t0; bf[nj * 2 + 0][1] = t1;
                bf[nj * 2 + 1][0] = t2; bf[nj * 2 + 1][1] = t3;
            }
            #pragma unroll
            for (int mi = 0; mi < 4; mi++)
                #pragma unroll
                for (int ni = 0; ni < 4; ni++) {
                    asm volatile(
                        "mma.sync.aligned.m16n8k16.row.col.f32.bf16.bf16.f32 "
                        "{%0,%1,%2,%3}, {%4,%5,%6,%7}, {%8,%9}, {%0,%1,%2,%3};"
                        : "+f"(acc[mi][ni][0]), "+f"(acc[mi][ni][1]),
                          "+f"(acc[mi][ni][2]), "+f"(acc[mi][ni][3])
                        : "r"(af[mi][0]), "r"(af[mi][1]), "r"(af[mi][2]), "r"(af[mi][3]),
                          "r"(bf[ni][0]), "r"(bf[ni][1]));
                }
        }

        __syncthreads();   // all LDSM done: stage st smem is now free for staging

        // prefetch tile i+2 into stage (st+2)%3 (distinct from st and st+1);
        // streams while the epilogue drains.
        if (t + 2 * GEMM_GRID < NTILES)
            load_tiles((st + 2) % NSTAGE, t + 2 * GEMM_GRID);

        // ---- warp-private staged epilogue: 4 chunks of 16 rows ----
        {
            int b  = t >> 8;
            int m0 = ((t >> 4) & 15) * 128;
            int n0 = (t & 15) * 128;
            float* ob = out + (size_t)b * SDIM * TDIM + n0 + wn * 32;
            float* stg = (float*)(smem_raw + st * STAGE_BYTES) + warp * WST_FLOATS;

            const int q  = lane >> 2;          // fragment row within chunk (0..7)
            const int jj = lane & 3;           // col pair index
            const int lr = lane >> 3;          // drain row offset (0..3)
            const int seg = lane & 7;          // 16B segment (0..7)

            #pragma unroll
            for (int c = 0; c < 4; c++) {
                const int mi = c;
                #pragma unroll
                for (int ni = 0; ni < 4; ni++) {
                    const int col = ni * 8 + jj * 2;
                    float2 v0 = make_float2(acc[mi][ni][0] * s, acc[mi][ni][1] * s);
                    float2 v1 = make_float2(acc[mi][ni][2] * s, acc[mi][ni][3] * s);
                    *(float2*)&stg[q * WST_PITCH + col]       = v0;
                    *(float2*)&stg[(q + 8) * WST_PITCH + col] = v1;
                }
                __syncwarp();
                #pragma unroll
                for (int i = 0; i < 4; i++) {
                    const int r = i * 4 + lr;                     // 0..15
                    float4 v = *(float4*)&stg[r * WST_PITCH + seg * 4];
                    const int gr = m0 + wm * 64 + c * 16 + r;
                    *(float4*)&ob[(size_t)gr * TDIM + seg * 4] = v;   // full 128B lines
                }
                __syncwarp();   // drain reads done before next chunk's STS overwrite
            }
        }

        st = (st + 1) % NSTAGE;
        t += GEMM_GRID;
    }
}

extern "C" void kernel_launch(void* const* d_in, const int* in_sizes, int n_in,
                              void* d_out, int out_size) {
    const float* A = (const float*)d_in[0];
    const float* B = (const float*)d_in[1];
    float* out = (float*)d_out;

    cudaFuncSetAttribute(k_gemm, cudaFuncAttributeMaxDynamicSharedMemorySize, SMEM_DYN);

    k_minmax<<<dim3(MM_BLOCKS, 1, 2), 256>>>(A, B);
    k_quant<<<dim3(2048, 1, 2), 256>>>(A, B);
    k_gemm<<<GEMM_GRID, 256, SMEM_DYN>>>(out);
}

// round 10
// speedup vs baseline: 1.1188x; 1.0836x over previous
#include <cuda_runtime.h>
#include <cuda_bf16.h>
#include <cstdint>

// Problem shape: A [64, 2048, 64], B [64, 64, 2048], out [64, 2048, 2048] (batch=4*16 flattened)
#define NBATCH 64
#define SDIM   2048
#define TDIM   2048
#define DDIM   64
#define NA_EL  (NBATCH * SDIM * DDIM)   // 8388608
#define NB_EL  (NBATCH * DDIM * TDIM)   // 8388608
#define MM_BLOCKS 1024                  // minmax blocks per tensor
#define NTILES  (NBATCH * 16 * 16)      // 16384 output tiles of 128x128
#define GEMM_GRID 296                   // 2 CTAs per SM (148 SMs)

// ---- device-global state (scratch; no allocations allowed) ----
__device__ float g_pmin[2][MM_BLOCKS], g_pmax[2][MM_BLOCKS];
__device__ float g_scale;
__device__ __nv_bfloat16 g_Aq[NA_EL];
__device__ __nv_bfloat16 g_Bq[NB_EL];

// ---- pass 1: per-tensor min/max partials (deterministic, no atomics, no reset) ----
// Exactly 8 grid-stride steps per thread -> fully unrolled for 8-deep LDG MLP.
__global__ void __launch_bounds__(256) k_minmax(const float* __restrict__ A,
                                               const float* __restrict__ B) {
    const int sel = blockIdx.z;
    const float4* x4 = (const float4*)(sel ? B : A);
    const int base = blockIdx.x * blockDim.x + threadIdx.x;
    const int stride = MM_BLOCKS * 256;           // n4 / stride == 8 exactly
    float4 v[8];
    #pragma unroll
    for (int j = 0; j < 8; j++) v[j] = x4[base + j * stride];
    float vmin = 0.0f, vmax = 0.0f;
    #pragma unroll
    for (int j = 0; j < 8; j++) {
        vmin = fminf(vmin, fminf(fminf(v[j].x, v[j].y), fminf(v[j].z, v[j].w)));
        vmax = fmaxf(vmax, fmaxf(fmaxf(v[j].x, v[j].y), fmaxf(v[j].z, v[j].w)));
    }
    #pragma unroll
    for (int o = 16; o > 0; o >>= 1) {
        vmin = fminf(vmin, __shfl_xor_sync(0xffffffffu, vmin, o));
        vmax = fmaxf(vmax, __shfl_xor_sync(0xffffffffu, vmax, o));
    }
    __shared__ float smin[8], smax[8];
    int wid = threadIdx.x >> 5, lane = threadIdx.x & 31;
    if (lane == 0) { smin[wid] = vmin; smax[wid] = vmax; }
    __syncthreads();
    if (threadIdx.x == 0) {
        float m = smin[0], M = smax[0];
        #pragma unroll
        for (int w = 1; w < 8; w++) { m = fminf(m, smin[w]); M = fmaxf(M, smax[w]); }
        g_pmin[sel][blockIdx.x] = m;
        g_pmax[sel][blockIdx.x] = M;
    }
}

// ---- pass 2: quant params (recomputed per block; deterministic) + fake-quant ----
__global__ void __launch_bounds__(256) k_quant(const float* __restrict__ A,
                                               const float* __restrict__ B) {
    const int t = threadIdx.x;
    float mA =  1e30f, MA = -1e30f, mB =  1e30f, MB = -1e30f;
    #pragma unroll
    for (int j = 0; j < MM_BLOCKS / 256; j++) {
        int idx = t + j * 256;
        mA = fminf(mA, g_pmin[0][idx]); MA = fmaxf(MA, g_pmax[0][idx]);
        mB = fminf(mB, g_pmin[1][idx]); MB = fmaxf(MB, g_pmax[1][idx]);
    }
    #pragma unroll
    for (int o = 16; o > 0; o >>= 1) {
        mA = fminf(mA, __shfl_xor_sync(0xffffffffu, mA, o));
        MA = fmaxf(MA, __shfl_xor_sync(0xffffffffu, MA, o));
        mB = fminf(mB, __shfl_xor_sync(0xffffffffu, mB, o));
        MB = fmaxf(MB, __shfl_xor_sync(0xffffffffu, MB, o));
    }
    __shared__ float sred[4][8];
    __shared__ float s_delta, s_zp;
    int wid = t >> 5, lane = t & 31;
    if (lane == 0) { sred[0][wid] = mA; sred[1][wid] = MA; sred[2][wid] = mB; sred[3][wid] = MB; }
    __syncthreads();
    if (t == 0) {
        float minA = sred[0][0], maxA = sred[1][0], minB = sred[2][0], maxB = sred[3][0];
        #pragma unroll
        for (int w = 1; w < 8; w++) {
            minA = fminf(minA, sred[0][w]); maxA = fmaxf(maxA, sred[1][w]);
            minB = fminf(minB, sred[2][w]); maxB = fmaxf(maxB, sred[3][w]);
        }
        float dA = fmaxf(__fdiv_rn(maxA - minA, 255.0f), 1e-8f);
        float dB = fmaxf(__fdiv_rn(maxB - minB, 255.0f), 1e-8f);
        if (blockIdx.z == 0) {
            s_delta = dA;
            s_zp = rintf(__fdiv_rn(-minA, dA));
        } else {
            s_delta = dB;
            s_zp = rintf(__fdiv_rn(-minB, dB));
        }
        if (blockIdx.x == 0 && blockIdx.z == 0) g_scale = dA * dB;
    }
    __syncthreads();
    const float delta = s_delta, zp = s_zp;

    const int sel = blockIdx.z;
    const float4* x4 = (const float4*)(sel ? B : A);
    uint2* o2 = (uint2*)(sel ? g_Bq : g_Aq);
    const int n4 = NA_EL / 4;
    #pragma unroll 4
    for (int i = blockIdx.x * blockDim.x + t; i < n4; i += 2048 * 256) {
        float4 v = x4[i];
        float q0 = fminf(fmaxf(rintf(__fdiv_rn(v.x, delta)) + zp, 0.0f), 255.0f) - zp;
        float q1 = fminf(fmaxf(rintf(__fdiv_rn(v.y, delta)) + zp, 0.0f), 255.0f) - zp;
        float q2 = fminf(fmaxf(rintf(__fdiv_rn(v.z, delta)) + zp, 0.0f), 255.0f) - zp;
        float q3 = fminf(fmaxf(rintf(__fdiv_rn(v.w, delta)) + zp, 0.0f), 255.0f) - zp;
        __nv_bfloat162 p0 = __floats2bfloat162_rn(q0, q1);
        __nv_bfloat162 p1 = __floats2bfloat162_rn(q2, q3);
        uint2 u;
        u.x = *(uint32_t*)&p0;
        u.y = *(uint32_t*)&p1;
        o2[i] = u;
    }
}

// ---- pass 3: persistent batched GEMM, CTA tile 128x128, 3-stage cp.async ----
// R7 structure (single barrier per tile, prefetch depth 2). Stores are fused
// into the FINAL k-step: each (mi,ni) fragment is scaled+stored right after its
// last MMA, spreading the store burst across the compute tail.
#define SA_ROWS 128
#define SA_COLS 72     // 64 + 8 pad (16B row shift -> no LDSM conflicts)
#define SB_ROWS 64
#define SB_COLS 136    // 128 + 8 pad
#define SA_BYTES (SA_ROWS * SA_COLS * 2)
#define SB_BYTES (SB_ROWS * SB_COLS * 2)
#define STAGE_BYTES (SA_BYTES + SB_BYTES)      // 35840
#define NSTAGE 3
#define SMEM_DYN (NSTAGE * STAGE_BYTES)        // 107520 B (2 CTAs = 215KB <= 228KB)

__device__ __forceinline__ void cpa16(void* dst, const void* src) {
    uint32_t d = (uint32_t)__cvta_generic_to_shared(dst);
    asm volatile("cp.async.cg.shared.global [%0], [%1], 16;" :: "r"(d), "l"(src));
}

__global__ void __launch_bounds__(256, 2) k_gemm(float* __restrict__ out) {
    extern __shared__ char smem_raw[];

    const int tid = threadIdx.x;
    const int warp = tid >> 5, lane = tid & 31;
    const int wm = warp >> 2;      // 0..1 -> 64 rows each
    const int wn = warp & 3;       // 0..3 -> 32 cols each

    const int ar = tid >> 3, ac = (tid & 7) * 8;          // A rows ar+{0,32,64,96}
    const int br = tid >> 4, bc = (tid & 15) * 8;         // B rows br+{0,16,32,48}

    auto stageA = [&](int st) -> __nv_bfloat16 (*)[SA_COLS] {
        return (__nv_bfloat16 (*)[SA_COLS])(smem_raw + st * STAGE_BYTES);
    };
    auto stageB = [&](int st) -> __nv_bfloat16 (*)[SB_COLS] {
        return (__nv_bfloat16 (*)[SB_COLS])(smem_raw + st * STAGE_BYTES + SA_BYTES);
    };

    auto load_tiles = [&](int st, int t) {
        int b  = t >> 8;
        int m0 = ((t >> 4) & 15) * 128;
        int n0 = (t & 15) * 128;
        const __nv_bfloat16* Ab = g_Aq + (size_t)b * SDIM * DDIM + (size_t)m0 * DDIM;
        const __nv_bfloat16* Bb = g_Bq + (size_t)b * DDIM * TDIM + n0;
        __nv_bfloat16 (*sA)[SA_COLS] = stageA(st);
        __nv_bfloat16 (*sB)[SB_COLS] = stageB(st);
        #pragma unroll
        for (int it = 0; it < 4; it++)
            cpa16(&sA[ar + it * 32][ac], Ab + (ar + it * 32) * DDIM + ac);
        #pragma unroll
        for (int it = 0; it < 4; it++)
            cpa16(&sB[br + it * 16][bc], Bb + (size_t)(br + it * 16) * TDIM + bc);
        asm volatile("cp.async.commit_group;");
    };

    const float s = g_scale;

    int t = blockIdx.x;
    int st = 0;
    if (t < NTILES) load_tiles(0, t);
    if (t + GEMM_GRID < NTILES) load_tiles(1, t + GEMM_GRID);

    while (t < NTILES) {
        if (t + GEMM_GRID < NTILES) {
            asm volatile("cp.async.wait_group 1;");   // this tile's group done
        } else {
            asm volatile("cp.async.wait_group 0;");
        }
        __syncthreads();   // single barrier per iteration

        __nv_bfloat16 (*sA)[SA_COLS] = stageA(st);
        __nv_bfloat16 (*sB)[SB_COLS] = stageB(st);

        // output addresses for the fused store tail
        const int b  = t >> 8;
        const int m0 = ((t >> 4) & 15) * 128;
        const int n0 = (t & 15) * 128;
        float* ob = out + (size_t)b * SDIM * TDIM;

        float acc[4][4][4];
        #pragma unroll
        for (int mi = 0; mi < 4; mi++)
            #pragma unroll
            for (int ni = 0; ni < 4; ni++)
                #pragma unroll
                for (int q = 0; q < 4; q++) acc[mi][ni][q] = 0.0f;

        #pragma unroll
        for (int ks = 0; ks < 4; ks++) {
            const int k0 = ks * 16;
            uint32_t af[4][4];
            #pragma unroll
            for (int mi = 0; mi < 4; mi++) {
                int r = wm * 64 + mi * 16 + (lane & 15);
                int c = k0 + (lane >> 4) * 8;
                uint32_t addr = (uint32_t)__cvta_generic_to_shared(&sA[r][c]);
                asm volatile(
                    "ldmatrix.sync.aligned.m8n8.x4.shared.b16 {%0,%1,%2,%3}, [%4];"
                    : "=r"(af[mi][0]), "=r"(af[mi][1]), "=r"(af[mi][2]), "=r"(af[mi][3])
                    : "r"(addr));
            }
            uint32_t bf[4][2];
            #pragma unroll
            for (int nj = 0; nj < 2; nj++) {
                int r = k0 + (lane & 7) + ((lane >> 3) & 1) * 8;
                int c = wn * 32 + nj * 16 + (lane >> 4) * 8;
                uint32_t addr = (uint32_t)__cvta_generic_to_shared(&sB[r][c]);
                uint32_t t0, t1, t2, t3;
                asm volatile(
                    "ldmatrix.sync.aligned.m8n8.x4.trans.shared.b16 {%0,%1,%2,%3}, [%4];"
                    : "=r"(t0), "=r"(t1), "=r"(t2), "=r"(t3)
                    : "r"(addr));
                bf[nj * 2 + 0][0] = t0; bf[nj * 2 + 0][1] = t1;
                bf[nj * 2 + 1][0] = t2; bf[nj * 2 + 1][1] = t3;
            }
            #pragma unroll
            for (int mi = 0; mi < 4; mi++)
                #pragma unroll
                for (int ni = 0; ni < 4; ni++) {
                    asm volatile(
                        "mma.sync.aligned.m16n8k16.row.col.f32.bf16.bf16.f32 "
                        "{%0,%1,%2,%3}, {%4,%5,%6,%7}, {%8,%9}, {%0,%1,%2,%3};"
                        : "+f"(acc[mi][ni][0]), "+f"(acc[mi][ni][1]),
                          "+f"(acc[mi][ni][2]), "+f"(acc[mi][ni][3])
                        : "r"(af[mi][0]), "r"(af[mi][1]), "r"(af[mi][2]), "r"(af[mi][3]),
                          "r"(bf[ni][0]), "r"(bf[ni][1]));
                    if (ks == 3) {
                        // final accumulation for this fragment: store immediately
                        int r = m0 + wm * 64 + mi * 16 + (lane >> 2);
                        int c = n0 + wn * 32 + ni * 8 + (lane & 3) * 2;
                        float2 v0 = make_float2(acc[mi][ni][0] * s, acc[mi][ni][1] * s);
                        float2 v1 = make_float2(acc[mi][ni][2] * s, acc[mi][ni][3] * s);
                        *(float2*)&ob[(size_t)r * TDIM + c]       = v0;
                        *(float2*)&ob[(size_t)(r + 8) * TDIM + c] = v1;
                    }
                }
        }

        // prefetch tile i+2 into stage (st+2)%3 (safe: != st and != st+1)
        if (t + 2 * GEMM_GRID < NTILES)
            load_tiles((st + 2) % NSTAGE, t + 2 * GEMM_GRID);

        st = (st + 1) % NSTAGE;
        t += GEMM_GRID;
    }
}

extern "C" void kernel_launch(void* const* d_in, const int* in_sizes, int n_in,
                              void* d_out, int out_size) {
    const float* A = (const float*)d_in[0];
    const float* B = (const float*)d_in[1];
    float* out = (float*)d_out;

    cudaFuncSetAttribute(k_gemm, cudaFuncAttributeMaxDynamicSharedMemorySize, SMEM_DYN);

    k_minmax<<<dim3(MM_BLOCKS, 1, 2), 256>>>(A, B);
    k_quant<<<dim3(2048, 1, 2), 256>>>(A, B);
    k_gemm<<<GEMM_GRID, 256, SMEM_DYN>>>(out);
}